// round 12
// baseline (speedup 1.0000x reference)
#include <cuda_runtime.h>
#include <cstdint>

#define B_ 64
#define Q_ 900
#define T_ 100
#define C_ 256
#define NTC 256          // cost kernel block
#define NTH 256          // hungarian block (8 warps: 4 matched + 4 free)
#define NCAND 128

// Scratch: transposed cost [B, T, Q] so hungarian reads contiguous rows.
__device__ float g_costT[(size_t)B_ * T_ * Q_];
// Per-(b,t) ~packed row-min key; 0 (static init) is the identity for atomicMax.
__device__ unsigned long long g_rowmin[B_ * T_];   // zero-initialized
// Per-row bottom-[100,128] candidate keys (order(c)<<32 | j), unsorted.
__device__ unsigned long long g_cand[(size_t)B_ * T_ * NCAND];
__device__ int g_ncand[B_ * T_];

__device__ __forceinline__ unsigned order_f(float f) {
    unsigned o = __float_as_uint(f);
    return (o & 0x80000000u) ? ~o : (o | 0x80000000u);
}
__device__ __forceinline__ float unorder_f(unsigned o) {
    return __uint_as_float((o & 0x80000000u) ? (o ^ 0x80000000u) : ~o);
}

// ---------------------------------------------------------------------------
// Kernel 1 (R11, known-good): one block per (b, 32-query tile). Label-sorted
// target order makes the logits gather semi-coalesced.
// ---------------------------------------------------------------------------
__global__ void __launch_bounds__(NTC) cost_fused_kernel(
        const float* __restrict__ logits,
        const float* __restrict__ pboxes,
        const int* __restrict__ labels,
        const float* __restrict__ tboxes,
        float* __restrict__ out) {
    __shared__ int    lab_s[T_];
    __shared__ int    ord_s[T_];
    __shared__ float4 tb_s[T_];       // cxcywh
    __shared__ float4 te_s[T_];       // xyxy
    __shared__ float  ta_s[T_];       // area
    __shared__ float4 pb_s[32];
    __shared__ float  tile[32][101];

    int b = blockIdx.y;
    int q0 = blockIdx.x * 32;
    int tid = threadIdx.x;

    if (tid < T_) {
        lab_s[tid] = labels[b * T_ + tid];
        float4 tb = __ldg(&((const float4*)tboxes)[b * T_ + tid]);
        tb_s[tid] = tb;
        float4 te;
        te.x = tb.x - 0.5f * tb.z; te.y = tb.y - 0.5f * tb.w;
        te.z = tb.x + 0.5f * tb.z; te.w = tb.y + 0.5f * tb.w;
        te_s[tid] = te;
        ta_s[tid] = (te.z - te.x) * (te.w - te.y);
    }
    if (tid < 32 && q0 + tid < Q_)
        pb_s[tid] = __ldg(&((const float4*)pboxes)[b * Q_ + q0 + tid]);
    __syncthreads();

    if (tid < T_) {                   // rank sort by (label, index)
        int lab = lab_s[tid];
        int rank = 0;
        for (int s = 0; s < T_; s++) {
            int ls = lab_s[s];
            rank += (ls < lab) || (ls == lab && s < tid);
        }
        ord_s[rank] = tid;
    }
    __syncthreads();

    int qq = tid >> 3;
    int q = q0 + qq;
    int t_lo = tid & 7;
    if (q < Q_) {
        float4 pb = pb_s[qq];
        float ax0 = pb.x - 0.5f * pb.z, ay0 = pb.y - 0.5f * pb.w;
        float ax1 = pb.x + 0.5f * pb.z, ay1 = pb.y + 0.5f * pb.w;
        float areaA = (ax1 - ax0) * (ay1 - ay0);
        const float* lrow = logits + ((long long)b * Q_ + q) * C_;

        #pragma unroll
        for (int s = 0; s < 13; s++) {
            int sidx = t_lo + (s << 3);
            if (sidx >= T_) break;
            int tt = ord_s[sidx];

            float cc = -__ldg(lrow + lab_s[tt]);
            float4 tb = tb_s[tt];
            float4 te = te_s[tt];

            float cb = fabsf(pb.x - tb.x) + fabsf(pb.y - tb.y);
            cb += fabsf(pb.z - tb.z);
            cb += fabsf(pb.w - tb.w);

            float wx = fminf(ax1, te.z) - fmaxf(ax0, te.x); wx = fmaxf(wx, 0.f);
            float wy = fminf(ay1, te.w) - fmaxf(ay0, te.y); wy = fmaxf(wy, 0.f);
            float inter = wx * wy;
            float uni = areaA + ta_s[tt] - inter;
            float iou = __fdividef(inter, uni);
            float ex = fmaxf(ax1, te.z) - fminf(ax0, te.x); ex = fmaxf(ex, 0.f);
            float ey = fmaxf(ay1, te.w) - fminf(ay0, te.y); ey = fmaxf(ey, 0.f);
            float enc = ex * ey;
            float giou = iou - __fdividef(enc - uni, enc);

            tile[qq][tt] = (cc + cb) - giou;
        }
    }
    __syncthreads();

    for (int idx = tid; idx < 32 * T_; idx += NTC) {
        int qq2 = idx / T_, tt = idx - qq2 * T_;
        int q2 = q0 + qq2;
        if (q2 < Q_)
            out[((size_t)b * Q_ + q2) * T_ + tt] = tile[qq2][tt];
    }
    for (int idx = tid; idx < 32 * T_; idx += NTC) {
        int tt = idx >> 5, q2 = q0 + (idx & 31);
        if (q2 < Q_)
            g_costT[((size_t)b * T_ + tt) * Q_ + q2] = tile[idx & 31][tt];
    }
    if (tid < T_) {
        unsigned long long best = ~0ull;
        int qmax = min(32, Q_ - q0);
        for (int k = 0; k < qmax; k++) {
            unsigned long long key =
                ((unsigned long long)order_f(tile[k][tid]) << 32) | (unsigned)(q0 + k);
            if (key < best) best = key;
        }
        atomicMax(&g_rowmin[b * T_ + tid], ~best);
    }
}

// ---------------------------------------------------------------------------
// Kernel 1.5 (R11, known-good): per-row bottom-[100,128] candidate selection.
// ---------------------------------------------------------------------------
__global__ void __launch_bounds__(256) cand_kernel() {
    int gw = (blockIdx.x * 256 + threadIdx.x) >> 5;    // row id = b*T + t
    int lane = threadIdx.x & 31;
    if (gw >= B_ * T_) return;
    const float* row = g_costT + (size_t)gw * Q_;

    unsigned long long key[29];
    #pragma unroll
    for (int k = 0; k < 29; k++) {
        int j = lane + (k << 5);
        key[k] = (j < Q_)
          ? (((unsigned long long)order_f(__ldg(row + j)) << 32) | (unsigned)j)
          : ~0ull;
    }

    unsigned lo = 0, hi = 0xFFFFFFFFu;
    unsigned tau = 0; int n = -1;
    for (int it = 0; it < 34 && n < 0; it++) {
        unsigned mid = (it < 32) ? (lo + ((hi - lo) >> 1)) : hi;
        int c = 0;
        #pragma unroll
        for (int k = 0; k < 29; k++)
            c += ((unsigned)(key[k] >> 32) <= mid) ? 1 : 0;
        c = __reduce_add_sync(0xFFFFFFFFu, c);
        if (c >= 100 && c <= NCAND) { tau = mid; n = c; }
        else if (c > NCAND) hi = mid;
        else lo = mid + 1;
    }

    bool tie = false; unsigned jcut = 0;
    if (n < 0) {
        tau = hi;
        int n1 = 0;
        #pragma unroll
        for (int k = 0; k < 29; k++)
            n1 += ((unsigned)(key[k] >> 32) < tau) ? 1 : 0;
        n1 = __reduce_add_sync(0xFFFFFFFFu, n1);
        int need = 100 - n1;
        unsigned jlo = 0, jhi = 1023;
        for (int it = 0; it < 10; it++) {
            unsigned jm = (jlo + jhi) >> 1;
            int c = 0;
            #pragma unroll
            for (int k = 0; k < 29; k++) {
                unsigned v = (unsigned)(key[k] >> 32);
                unsigned j = (unsigned)(key[k] & 0xFFFFFFFFu);
                c += (v == tau && j <= jm) ? 1 : 0;
            }
            c = __reduce_add_sync(0xFFFFFFFFu, c);
            if (c >= need) jhi = jm; else jlo = jm + 1;
        }
        jcut = jhi; tie = true;
    }

    unsigned long long* dst = g_cand + ((size_t)gw << 7);
    int base = 0;
    #pragma unroll
    for (int k = 0; k < 29; k++) {
        unsigned v = (unsigned)(key[k] >> 32);
        unsigned j = (unsigned)(key[k] & 0xFFFFFFFFu);
        bool qv = tie ? ((v < tau) || (v == tau && j <= jcut)) : (v <= tau);
        qv = qv && (j < (unsigned)Q_);
        unsigned mask = __ballot_sync(0xFFFFFFFFu, qv);
        if (qv) dst[base + __popc(mask & ((1u << lane) - 1))] = key[k];
        base += __popc(mask);
    }
    if (lane == 0) g_ncand[gw] = base;
}

// ---------------------------------------------------------------------------
// Kernel 2: JV, greedy rowmin init + matched/free-split SAP with the matched
// sub-matrix cached in shared memory (cmat[100 rows][100 slots]).
// ---------------------------------------------------------------------------
__global__ void __launch_bounds__(NTH) hungarian_kernel(float* __restrict__ out,
                                                        int writeIdx) {
    int b = blockIdx.x;
    const float* cost = g_costT + (size_t)b * T_ * Q_;

    __shared__ float cmat[T_ * 100];      // [row i][matched slot] = cost[i][mlist[slot]]
    __shared__ float u[T_ + 1];
    __shared__ short p[Q_];               // row matched to col j (-1 free)
    __shared__ short sway[Q_];            // predecessor column
    __shared__ unsigned long long keybuf[2][8];
    __shared__ short mlist[T_];
    __shared__ int ncand_s[T_];
    __shared__ int argj[T_];
    __shared__ unsigned char rowmatch[T_];
    __shared__ short colarr[T_];
    __shared__ int nm_s;

    int tid = threadIdx.x, lane = tid & 31, wid = tid >> 5;

    for (int j = tid; j < Q_; j += NTH) p[j] = -1;
    if (tid < T_) {
        unsigned long long k = ~g_rowmin[b * T_ + tid];
        argj[tid] = (int)(k & 0xFFFFFFFFu);
        u[tid] = unorder_f((unsigned)(k >> 32));
        ncand_s[tid] = g_ncand[b * T_ + tid];
    }
    if (tid == 0) u[T_] = 0.f;
    __syncthreads();

    if (tid == 0) {
        int nm = 0;
        for (int i = 0; i < T_; i++) {
            int j = argj[i];
            if (p[j] < 0) { p[j] = (short)i; rowmatch[i] = 1; mlist[nm++] = (short)j; }
            else rowmatch[i] = 0;
        }
        nm_s = nm;
    }
    __syncthreads();

    // fill cmat for the initial matched set (one-time scattered gather)
    {
        int nm = nm_s;
        for (int idx = tid; idx < T_ * nm; idx += NTH) {
            int i = idx / nm;
            int s = idx - i * nm;
            cmat[i * 100 + s] = __ldg(cost + (size_t)i * Q_ + (int)mlist[s]);
        }
    }
    __syncthreads();

    // per-slot matched-column registers (slot = tid, threads 0..127)
    int myj = -1;
    float myv = 0.f;
    unsigned myminv = ~0u;
    bool myused = false;

    for (int i = 0; i < T_; i++) {
        if (rowmatch[i]) continue;
        int nm = nm_s;
        if (tid < nm && myj < 0) { myj = (int)mlist[tid]; myv = 0.f; }
        myminv = 0xFFFFFFFEu; myused = false;
        unsigned long long freebest = ~0ull;
        int freepred = Q_;

        int j0 = Q_, i0 = i, iter = 0, j1;
        float shift = 0.f, Sf;

        while (true) {
            float base = shift - u[i0];
            unsigned bo = 0xFFFFFFFFu, bj = 0xFFFFFFFFu;
            if (tid < 128) {                          // matched side: smem only
                if (tid < nm && !myused) {
                    float cur = cmat[i0 * 100 + tid] - myv + base;
                    unsigned co = order_f(cur);
                    if (co < myminv) { myminv = co; sway[myj] = (short)j0; }
                    bo = myminv; bj = (unsigned)myj;
                }
            } else {                                  // free side (candidates)
                int ci = tid - 128;
                if (ci < ncand_s[i0]) {
                    unsigned long long ck =
                        __ldg(&g_cand[((size_t)(b * T_ + i0) << 7) + ci]);
                    int j = (int)(ck & 0xFFFFFFFFu);
                    if (p[j] < 0) {
                        float val = unorder_f((unsigned)(ck >> 32)) + base;
                        bo = order_f(val); bj = (unsigned)j;
                    }
                }
            }
            unsigned m = __reduce_min_sync(0xFFFFFFFFu, bo);
            unsigned jc = (bo == m) ? bj : 0xFFFFFFFFu;
            unsigned jm = __reduce_min_sync(0xFFFFFFFFu, jc);
            int buf = iter & 1;
            if (lane == 0) keybuf[buf][wid] = ((unsigned long long)m << 32) | jm;
            __syncthreads();

            const unsigned long long* kb = keybuf[buf];
            unsigned long long m0 = kb[0] < kb[2] ? kb[0] : kb[2];
            unsigned long long m1 = kb[1] < kb[3] ? kb[1] : kb[3];
            unsigned long long mpart = m0 < m1 ? m0 : m1;
            unsigned long long f0 = kb[4] < kb[6] ? kb[4] : kb[6];
            unsigned long long f1 = kb[5] < kb[7] ? kb[5] : kb[7];
            unsigned long long fpart = f0 < f1 ? f0 : f1;
            if (fpart < freebest) { freebest = fpart; freepred = j0; }
            unsigned long long tot = mpart < freebest ? mpart : freebest;
            j1 = (int)(tot & 0xFFFFFFFFu);
            Sf = unorder_f((unsigned)(tot >> 32));

            int i0n = (int)p[j1];
            if (i0n < 0) break;                       // free column -> augment

            if (myj == j1) myused = true;             // owner freezes its dist
            j0 = j1; i0 = i0n; shift = Sf; iter++;
        }

        // deferred dual updates (used matched columns only; free v stays 0)
        if (tid < nm && myused) {
            float diff = Sf - unorder_f(myminv);
            myv -= diff;
            u[(int)p[myj]] += diff;                   // rows distinct
        }
        if (tid == 0) u[i] += Sf;
        __syncthreads();                              // duals read p pre-augment

        // append new matched column j1 to cmat (slot nm)
        if (tid < T_)
            cmat[tid * 100 + nm] = __ldg(cost + (size_t)tid * Q_ + j1);

        if (tid == 0) {
            sway[j1] = (short)freepred;
            int j = j1;
            while (j != Q_) {
                int jn = (int)sway[j];
                p[j] = (jn == Q_) ? (short)i : p[jn];
                j = jn;
            }
            rowmatch[i] = 1;
            mlist[nm] = (short)j1;                    // new matched column
            nm_s = nm + 1;
        }
        __syncthreads();
    }

    // write indices sorted by query (rank via counting)
    for (int j = tid; j < Q_; j += NTH) {
        int r = (int)p[j];
        if (r >= 0) colarr[r] = (short)j;
    }
    __syncthreads();

    if (writeIdx) {
        float* oidx = out + (size_t)B_ * Q_ * T_;
        if (tid < T_) {
            int c = (int)colarr[tid];
            int rank = 0;
            for (int s = 0; s < T_; s++) rank += ((int)colarr[s] < c);
            oidx[(size_t)b * T_ + rank] = (float)c;                      // pred_idx
            oidx[(size_t)B_ * T_ + (size_t)b * T_ + rank] = (float)tid;  // tgt_idx
        }
    }

    // reset rowmin identity for the next graph replay
    if (tid < T_) g_rowmin[b * T_ + tid] = 0ull;
}

// ---------------------------------------------------------------------------
extern "C" void kernel_launch(void* const* d_in, const int* in_sizes, int n_in,
                              void* d_out, int out_size) {
    const float* logits = (const float*)d_in[0];
    const float* pboxes = (const float*)d_in[1];
    const int*   labels = (const int*)d_in[2];
    const float* tboxes = (const float*)d_in[3];
    float* out = (float*)d_out;

    dim3 tg((Q_ + 31) / 32, B_);
    cost_fused_kernel<<<tg, NTC>>>(logits, pboxes, labels, tboxes, out);

    int nrows = B_ * T_;
    cand_kernel<<<(nrows * 32 + 255) / 256, 256>>>();

    int writeIdx = (out_size >= (int)((long long)B_ * Q_ * T_ + 2LL * B_ * T_)) ? 1 : 0;
    hungarian_kernel<<<B_, NTH>>>(out, writeIdx);
}

// round 13
// speedup vs baseline: 1.0529x; 1.0529x over previous
#include <cuda_runtime.h>
#include <cstdint>

#define B_ 64
#define Q_ 900
#define T_ 100
#define C_ 256
#define NTC 256          // cost kernel block
#define NTH 256          // hungarian block (8 warps: 4 matched + 4 free)
#define NCAND 128
#define CST 101          // cmat padded stride (conflict-free)

// Scratch: transposed cost [B, T, Q] so hungarian reads contiguous rows.
__device__ float g_costT[(size_t)B_ * T_ * Q_];
// Per-(b,t) ~packed row-min key; 0 (static init) is the identity for atomicMax.
__device__ unsigned long long g_rowmin[B_ * T_];   // zero-initialized
// Per-row bottom-[100,128] candidate keys (order(c)<<32 | j), unsorted.
__device__ unsigned long long g_cand[(size_t)B_ * T_ * NCAND];
__device__ int g_ncand[B_ * T_];

__device__ __forceinline__ unsigned order_f(float f) {
    unsigned o = __float_as_uint(f);
    return (o & 0x80000000u) ? ~o : (o | 0x80000000u);
}
__device__ __forceinline__ float unorder_f(unsigned o) {
    return __uint_as_float((o & 0x80000000u) ? (o ^ 0x80000000u) : ~o);
}

// ---------------------------------------------------------------------------
// Kernel 1 (R11, known-good): one block per (b, 32-query tile). Label-sorted
// target order makes the logits gather semi-coalesced.
// ---------------------------------------------------------------------------
__global__ void __launch_bounds__(NTC) cost_fused_kernel(
        const float* __restrict__ logits,
        const float* __restrict__ pboxes,
        const int* __restrict__ labels,
        const float* __restrict__ tboxes,
        float* __restrict__ out) {
    __shared__ int    lab_s[T_];
    __shared__ int    ord_s[T_];
    __shared__ float4 tb_s[T_];       // cxcywh
    __shared__ float4 te_s[T_];       // xyxy
    __shared__ float  ta_s[T_];       // area
    __shared__ float4 pb_s[32];
    __shared__ float  tile[32][101];

    int b = blockIdx.y;
    int q0 = blockIdx.x * 32;
    int tid = threadIdx.x;

    if (tid < T_) {
        lab_s[tid] = labels[b * T_ + tid];
        float4 tb = __ldg(&((const float4*)tboxes)[b * T_ + tid]);
        tb_s[tid] = tb;
        float4 te;
        te.x = tb.x - 0.5f * tb.z; te.y = tb.y - 0.5f * tb.w;
        te.z = tb.x + 0.5f * tb.z; te.w = tb.y + 0.5f * tb.w;
        te_s[tid] = te;
        ta_s[tid] = (te.z - te.x) * (te.w - te.y);
    }
    if (tid < 32 && q0 + tid < Q_)
        pb_s[tid] = __ldg(&((const float4*)pboxes)[b * Q_ + q0 + tid]);
    __syncthreads();

    if (tid < T_) {                   // rank sort by (label, index)
        int lab = lab_s[tid];
        int rank = 0;
        for (int s = 0; s < T_; s++) {
            int ls = lab_s[s];
            rank += (ls < lab) || (ls == lab && s < tid);
        }
        ord_s[rank] = tid;
    }
    __syncthreads();

    int qq = tid >> 3;
    int q = q0 + qq;
    int t_lo = tid & 7;
    if (q < Q_) {
        float4 pb = pb_s[qq];
        float ax0 = pb.x - 0.5f * pb.z, ay0 = pb.y - 0.5f * pb.w;
        float ax1 = pb.x + 0.5f * pb.z, ay1 = pb.y + 0.5f * pb.w;
        float areaA = (ax1 - ax0) * (ay1 - ay0);
        const float* lrow = logits + ((long long)b * Q_ + q) * C_;

        #pragma unroll
        for (int s = 0; s < 13; s++) {
            int sidx = t_lo + (s << 3);
            if (sidx >= T_) break;
            int tt = ord_s[sidx];

            float cc = -__ldg(lrow + lab_s[tt]);
            float4 tb = tb_s[tt];
            float4 te = te_s[tt];

            float cb = fabsf(pb.x - tb.x) + fabsf(pb.y - tb.y);
            cb += fabsf(pb.z - tb.z);
            cb += fabsf(pb.w - tb.w);

            float wx = fminf(ax1, te.z) - fmaxf(ax0, te.x); wx = fmaxf(wx, 0.f);
            float wy = fminf(ay1, te.w) - fmaxf(ay0, te.y); wy = fmaxf(wy, 0.f);
            float inter = wx * wy;
            float uni = areaA + ta_s[tt] - inter;
            float iou = __fdividef(inter, uni);
            float ex = fmaxf(ax1, te.z) - fminf(ax0, te.x); ex = fmaxf(ex, 0.f);
            float ey = fmaxf(ay1, te.w) - fminf(ay0, te.y); ey = fmaxf(ey, 0.f);
            float enc = ex * ey;
            float giou = iou - __fdividef(enc - uni, enc);

            tile[qq][tt] = (cc + cb) - giou;
        }
    }
    __syncthreads();

    for (int idx = tid; idx < 32 * T_; idx += NTC) {
        int qq2 = idx / T_, tt = idx - qq2 * T_;
        int q2 = q0 + qq2;
        if (q2 < Q_)
            out[((size_t)b * Q_ + q2) * T_ + tt] = tile[qq2][tt];
    }
    for (int idx = tid; idx < 32 * T_; idx += NTC) {
        int tt = idx >> 5, q2 = q0 + (idx & 31);
        if (q2 < Q_)
            g_costT[((size_t)b * T_ + tt) * Q_ + q2] = tile[idx & 31][tt];
    }
    if (tid < T_) {
        unsigned long long best = ~0ull;
        int qmax = min(32, Q_ - q0);
        for (int k = 0; k < qmax; k++) {
            unsigned long long key =
                ((unsigned long long)order_f(tile[k][tid]) << 32) | (unsigned)(q0 + k);
            if (key < best) best = key;
        }
        atomicMax(&g_rowmin[b * T_ + tid], ~best);
    }
}

// ---------------------------------------------------------------------------
// Kernel 1.5 (R11, known-good): per-row bottom-[100,128] candidate selection.
// ---------------------------------------------------------------------------
__global__ void __launch_bounds__(256) cand_kernel() {
    int gw = (blockIdx.x * 256 + threadIdx.x) >> 5;    // row id = b*T + t
    int lane = threadIdx.x & 31;
    if (gw >= B_ * T_) return;
    const float* row = g_costT + (size_t)gw * Q_;

    unsigned long long key[29];
    #pragma unroll
    for (int k = 0; k < 29; k++) {
        int j = lane + (k << 5);
        key[k] = (j < Q_)
          ? (((unsigned long long)order_f(__ldg(row + j)) << 32) | (unsigned)j)
          : ~0ull;
    }

    unsigned lo = 0, hi = 0xFFFFFFFFu;
    unsigned tau = 0; int n = -1;
    for (int it = 0; it < 34 && n < 0; it++) {
        unsigned mid = (it < 32) ? (lo + ((hi - lo) >> 1)) : hi;
        int c = 0;
        #pragma unroll
        for (int k = 0; k < 29; k++)
            c += ((unsigned)(key[k] >> 32) <= mid) ? 1 : 0;
        c = __reduce_add_sync(0xFFFFFFFFu, c);
        if (c >= 100 && c <= NCAND) { tau = mid; n = c; }
        else if (c > NCAND) hi = mid;
        else lo = mid + 1;
    }

    bool tie = false; unsigned jcut = 0;
    if (n < 0) {
        tau = hi;
        int n1 = 0;
        #pragma unroll
        for (int k = 0; k < 29; k++)
            n1 += ((unsigned)(key[k] >> 32) < tau) ? 1 : 0;
        n1 = __reduce_add_sync(0xFFFFFFFFu, n1);
        int need = 100 - n1;
        unsigned jlo = 0, jhi = 1023;
        for (int it = 0; it < 10; it++) {
            unsigned jm = (jlo + jhi) >> 1;
            int c = 0;
            #pragma unroll
            for (int k = 0; k < 29; k++) {
                unsigned v = (unsigned)(key[k] >> 32);
                unsigned j = (unsigned)(key[k] & 0xFFFFFFFFu);
                c += (v == tau && j <= jm) ? 1 : 0;
            }
            c = __reduce_add_sync(0xFFFFFFFFu, c);
            if (c >= need) jhi = jm; else jlo = jm + 1;
        }
        jcut = jhi; tie = true;
    }

    unsigned long long* dst = g_cand + ((size_t)gw << 7);
    int base = 0;
    #pragma unroll
    for (int k = 0; k < 29; k++) {
        unsigned v = (unsigned)(key[k] >> 32);
        unsigned j = (unsigned)(key[k] & 0xFFFFFFFFu);
        bool qv = tie ? ((v < tau) || (v == tau && j <= jcut)) : (v <= tau);
        qv = qv && (j < (unsigned)Q_);
        unsigned mask = __ballot_sync(0xFFFFFFFFu, qv);
        if (qv) dst[base + __popc(mask & ((1u << lane) - 1))] = key[k];
        base += __popc(mask);
    }
    if (lane == 0) g_ncand[gw] = base;
}

// ---------------------------------------------------------------------------
// Kernel 2: JV, greedy rowmin init + matched/free-split SAP. Hybrid cache:
// initial matched columns live in smem (coalesced fill from out[B,Q,T]);
// columns matched later fall back to direct costT loads (no append cost).
// ---------------------------------------------------------------------------
__global__ void __launch_bounds__(NTH) hungarian_kernel(float* __restrict__ out,
                                                        int writeIdx) {
    int b = blockIdx.x;
    const float* cost = g_costT + (size_t)b * T_ * Q_;

    __shared__ float cmat[T_ * CST];      // [row i][init slot s]
    __shared__ float u[T_ + 1];
    __shared__ short p[Q_];
    __shared__ short sway[Q_];
    __shared__ unsigned long long keybuf[2][8];
    __shared__ short mlist[T_];
    __shared__ int ncand_s[T_];
    __shared__ int argj[T_];
    __shared__ unsigned char rowmatch[T_];
    __shared__ short colarr[T_];
    __shared__ int nm_s;

    int tid = threadIdx.x, lane = tid & 31, wid = tid >> 5;

    for (int j = tid; j < Q_; j += NTH) p[j] = -1;
    if (tid < T_) {
        unsigned long long k = ~g_rowmin[b * T_ + tid];
        argj[tid] = (int)(k & 0xFFFFFFFFu);
        u[tid] = unorder_f((unsigned)(k >> 32));
        ncand_s[tid] = g_ncand[b * T_ + tid];
    }
    if (tid == 0) u[T_] = 0.f;
    __syncthreads();

    if (tid == 0) {
        int nm = 0;
        for (int i = 0; i < T_; i++) {
            int j = argj[i];
            if (p[j] < 0) { p[j] = (short)i; rowmatch[i] = 1; mlist[nm++] = (short)j; }
            else rowmatch[i] = 0;
        }
        nm_s = nm;
    }
    __syncthreads();

    const int nm0 = nm_s;                 // slots cached in smem

    // coalesced cmat fill from out[B,Q,T]: for fixed slot s, i is contiguous
    {
        const float* obase = out + (size_t)b * Q_ * T_;
        for (int idx = tid; idx < nm0 * T_; idx += NTH) {
            int s = idx / T_;
            int i = idx - s * T_;
            cmat[i * CST + s] = __ldg(obase + (size_t)(int)mlist[s] * T_ + i);
        }
    }
    __syncthreads();

    // per-slot matched-column registers (slot = tid, threads 0..127)
    int myj = -1;
    float myv = 0.f;
    unsigned myminv = ~0u;
    bool myused = false;

    for (int i = 0; i < T_; i++) {
        if (rowmatch[i]) continue;
        int nm = nm_s;
        if (tid < nm && myj < 0) { myj = (int)mlist[tid]; myv = 0.f; }
        myminv = 0xFFFFFFFEu; myused = false;
        unsigned long long freebest = ~0ull;
        int freepred = Q_;

        int j0 = Q_, i0 = i, iter = 0, j1;
        float shift = 0.f, Sf;

        while (true) {
            float base = shift - u[i0];
            unsigned bo = 0xFFFFFFFFu, bj = 0xFFFFFFFFu;
            if (tid < 128) {                          // matched side
                if (tid < nm && !myused) {
                    float c = (tid < nm0)
                        ? cmat[i0 * CST + tid]
                        : __ldg(cost + (size_t)i0 * Q_ + myj);
                    float cur = c - myv + base;
                    unsigned co = order_f(cur);
                    if (co < myminv) { myminv = co; sway[myj] = (short)j0; }
                    bo = myminv; bj = (unsigned)myj;
                }
            } else {                                  // free side (candidates)
                int ci = tid - 128;
                if (ci < ncand_s[i0]) {
                    unsigned long long ck =
                        __ldg(&g_cand[((size_t)(b * T_ + i0) << 7) + ci]);
                    int j = (int)(ck & 0xFFFFFFFFu);
                    if (p[j] < 0) {
                        float val = unorder_f((unsigned)(ck >> 32)) + base;
                        bo = order_f(val); bj = (unsigned)j;
                    }
                }
            }
            unsigned m = __reduce_min_sync(0xFFFFFFFFu, bo);
            unsigned jc = (bo == m) ? bj : 0xFFFFFFFFu;
            unsigned jm = __reduce_min_sync(0xFFFFFFFFu, jc);
            int buf = iter & 1;
            if (lane == 0) keybuf[buf][wid] = ((unsigned long long)m << 32) | jm;
            __syncthreads();

            const unsigned long long* kb = keybuf[buf];
            unsigned long long m0 = kb[0] < kb[2] ? kb[0] : kb[2];
            unsigned long long m1 = kb[1] < kb[3] ? kb[1] : kb[3];
            unsigned long long mpart = m0 < m1 ? m0 : m1;
            unsigned long long f0 = kb[4] < kb[6] ? kb[4] : kb[6];
            unsigned long long f1 = kb[5] < kb[7] ? kb[5] : kb[7];
            unsigned long long fpart = f0 < f1 ? f0 : f1;
            if (fpart < freebest) { freebest = fpart; freepred = j0; }
            unsigned long long tot = mpart < freebest ? mpart : freebest;
            j1 = (int)(tot & 0xFFFFFFFFu);
            Sf = unorder_f((unsigned)(tot >> 32));

            int i0n = (int)p[j1];
            if (i0n < 0) break;                       // free column -> augment

            if (myj == j1) myused = true;             // owner freezes its dist
            j0 = j1; i0 = i0n; shift = Sf; iter++;
        }

        // deferred dual updates (used matched columns only; free v stays 0)
        if (tid < nm && myused) {
            float diff = Sf - unorder_f(myminv);
            myv -= diff;
            u[(int)p[myj]] += diff;                   // rows distinct
        }
        if (tid == 0) u[i] += Sf;
        __syncthreads();                              // duals read p pre-augment

        if (tid == 0) {
            sway[j1] = (short)freepred;
            int j = j1;
            while (j != Q_) {
                int jn = (int)sway[j];
                p[j] = (jn == Q_) ? (short)i : p[jn];
                j = jn;
            }
            rowmatch[i] = 1;
            mlist[nm_s] = (short)j1;                  // new matched column
            nm_s = nm_s + 1;
        }
        __syncthreads();
    }

    // write indices sorted by query (rank via counting)
    for (int j = tid; j < Q_; j += NTH) {
        int r = (int)p[j];
        if (r >= 0) colarr[r] = (short)j;
    }
    __syncthreads();

    if (writeIdx) {
        float* oidx = out + (size_t)B_ * Q_ * T_;
        if (tid < T_) {
            int c = (int)colarr[tid];
            int rank = 0;
            for (int s = 0; s < T_; s++) rank += ((int)colarr[s] < c);
            oidx[(size_t)b * T_ + rank] = (float)c;                      // pred_idx
            oidx[(size_t)B_ * T_ + (size_t)b * T_ + rank] = (float)tid;  // tgt_idx
        }
    }

    // reset rowmin identity for the next graph replay
    if (tid < T_) g_rowmin[b * T_ + tid] = 0ull;
}

// ---------------------------------------------------------------------------
extern "C" void kernel_launch(void* const* d_in, const int* in_sizes, int n_in,
                              void* d_out, int out_size) {
    const float* logits = (const float*)d_in[0];
    const float* pboxes = (const float*)d_in[1];
    const int*   labels = (const int*)d_in[2];
    const float* tboxes = (const float*)d_in[3];
    float* out = (float*)d_out;

    dim3 tg((Q_ + 31) / 32, B_);
    cost_fused_kernel<<<tg, NTC>>>(logits, pboxes, labels, tboxes, out);

    int nrows = B_ * T_;
    cand_kernel<<<(nrows * 32 + 255) / 256, 256>>>();

    int writeIdx = (out_size >= (int)((long long)B_ * Q_ * T_ + 2LL * B_ * T_)) ? 1 : 0;
    hungarian_kernel<<<B_, NTH>>>(out, writeIdx);
}

// round 14
// speedup vs baseline: 1.1321x; 1.0753x over previous
#include <cuda_runtime.h>
#include <cstdint>

#define B_ 64
#define Q_ 900
#define T_ 100
#define C_ 256
#define NTC 256          // cost kernel block
#define NTH 256          // hungarian block (8 warps: 4 matched + 4 free)
#define NCAND 128

// Scratch: transposed cost [B, T, Q] so hungarian reads contiguous rows.
__device__ float g_costT[(size_t)B_ * T_ * Q_];
// Per-(b,t) ~packed row-min key; 0 (static init) is the identity for atomicMax.
__device__ unsigned long long g_rowmin[B_ * T_];   // zero-initialized
// Per-row bottom-[100,128] candidate keys (order(c)<<32 | j), unsorted.
__device__ unsigned long long g_cand[(size_t)B_ * T_ * NCAND];
__device__ int g_ncand[B_ * T_];

__device__ __forceinline__ unsigned order_f(float f) {
    unsigned o = __float_as_uint(f);
    return (o & 0x80000000u) ? ~o : (o | 0x80000000u);
}
__device__ __forceinline__ float unorder_f(unsigned o) {
    return __uint_as_float((o & 0x80000000u) ? (o ^ 0x80000000u) : ~o);
}

// ---------------------------------------------------------------------------
// Kernel 1: one block per (b, 32-query tile). Label-sorted target order for
// the logits gather; 2 queries per thread to amortize tb-side smem loads;
// enclose box via the wA+wB-overlap identity.
// ---------------------------------------------------------------------------
__global__ void __launch_bounds__(NTC) cost_fused_kernel(
        const float* __restrict__ logits,
        const float* __restrict__ pboxes,
        const int* __restrict__ labels,
        const float* __restrict__ tboxes,
        float* __restrict__ out) {
    __shared__ int    lab_s[T_];
    __shared__ int    ord_s[T_];
    __shared__ float4 tb_s[T_];       // cxcywh
    __shared__ float4 te_s[T_];       // xyxy
    __shared__ float  ta_s[T_];       // area
    __shared__ float4 pb_s[32];
    __shared__ float  tile[32][101];

    int b = blockIdx.y;
    int q0 = blockIdx.x * 32;
    int tid = threadIdx.x;

    if (tid < T_) {
        lab_s[tid] = labels[b * T_ + tid];
        float4 tb = __ldg(&((const float4*)tboxes)[b * T_ + tid]);
        tb_s[tid] = tb;
        float4 te;
        te.x = tb.x - 0.5f * tb.z; te.y = tb.y - 0.5f * tb.w;
        te.z = tb.x + 0.5f * tb.z; te.w = tb.y + 0.5f * tb.w;
        te_s[tid] = te;
        ta_s[tid] = (te.z - te.x) * (te.w - te.y);
    }
    if (tid < 32 && q0 + tid < Q_)
        pb_s[tid] = __ldg(&((const float4*)pboxes)[b * Q_ + q0 + tid]);
    __syncthreads();

    if (tid < T_) {                   // rank sort by (label, index)
        int lab = lab_s[tid];
        int rank = 0;
        for (int s = 0; s < T_; s++) {
            int ls = lab_s[s];
            rank += (ls < lab) || (ls == lab && s < tid);
        }
        ord_s[rank] = tid;
    }
    __syncthreads();

    // thread owns queries qA = q0 + (tid>>4) and qB = qA + 16, t-slots tid&15
    int qlo = tid >> 4;               // 0..15
    int t_lo = tid & 15;              // 0..15
    int qA = q0 + qlo, qB = qA + 16;
    bool vA = qA < Q_, vB = qB < Q_;

    float4 pbA = pb_s[qlo];
    float4 pbB = pb_s[qlo + 16];
    float axA0 = pbA.x - 0.5f * pbA.z, ayA0 = pbA.y - 0.5f * pbA.w;
    float axA1 = pbA.x + 0.5f * pbA.z, ayA1 = pbA.y + 0.5f * pbA.w;
    float areaAA = (axA1 - axA0) * (ayA1 - ayA0);
    float axB0 = pbB.x - 0.5f * pbB.z, ayB0 = pbB.y - 0.5f * pbB.w;
    float axB1 = pbB.x + 0.5f * pbB.z, ayB1 = pbB.y + 0.5f * pbB.w;
    float areaAB = (axB1 - axB0) * (ayB1 - ayB0);
    const float* lrowA = logits + ((long long)b * Q_ + (vA ? qA : q0)) * C_;
    const float* lrowB = logits + ((long long)b * Q_ + (vB ? qB : q0)) * C_;

    #pragma unroll
    for (int s = 0; s < 7; s++) {
        int sidx = t_lo + (s << 4);
        if (sidx >= T_) break;
        int tt = ord_s[sidx];         // label-sorted order -> coalesced gather
        int lab = lab_s[tt];
        float4 tb = tb_s[tt];
        float4 te = te_s[tt];
        float ta = ta_s[tt];

        float ccA = vA ? -__ldg(lrowA + lab) : 0.f;
        float ccB = vB ? -__ldg(lrowB + lab) : 0.f;

        // query A
        {
            float cb = fabsf(pbA.x - tb.x) + fabsf(pbA.y - tb.y);
            cb += fabsf(pbA.z - tb.z);
            cb += fabsf(pbA.w - tb.w);
            float wxu = fminf(axA1, te.z) - fmaxf(axA0, te.x);
            float wyu = fminf(ayA1, te.w) - fmaxf(ayA0, te.y);
            float inter = fmaxf(wxu, 0.f) * fmaxf(wyu, 0.f);
            float uni = areaAA + ta - inter;
            float ex = (pbA.z + tb.z) - wxu;   // = max(x1)-min(x0), exact in reals
            float ey = (pbA.w + tb.w) - wyu;
            float enc = ex * ey;
            float giou = __fdividef(inter, uni) - __fdividef(enc - uni, enc);
            tile[qlo][tt] = (ccA + cb) - giou;
        }
        // query B
        {
            float cb = fabsf(pbB.x - tb.x) + fabsf(pbB.y - tb.y);
            cb += fabsf(pbB.z - tb.z);
            cb += fabsf(pbB.w - tb.w);
            float wxu = fminf(axB1, te.z) - fmaxf(axB0, te.x);
            float wyu = fminf(ayB1, te.w) - fmaxf(ayB0, te.y);
            float inter = fmaxf(wxu, 0.f) * fmaxf(wyu, 0.f);
            float uni = areaAB + ta - inter;
            float ex = (pbB.z + tb.z) - wxu;
            float ey = (pbB.w + tb.w) - wyu;
            float enc = ex * ey;
            float giou = __fdividef(inter, uni) - __fdividef(enc - uni, enc);
            tile[qlo + 16][tt] = (ccB + cb) - giou;
        }
    }
    __syncthreads();

    for (int idx = tid; idx < 32 * T_; idx += NTC) {
        int qq2 = idx / T_, tt = idx - qq2 * T_;
        int q2 = q0 + qq2;
        if (q2 < Q_)
            out[((size_t)b * Q_ + q2) * T_ + tt] = tile[qq2][tt];
    }
    for (int idx = tid; idx < 32 * T_; idx += NTC) {
        int tt = idx >> 5, q2 = q0 + (idx & 31);
        if (q2 < Q_)
            g_costT[((size_t)b * T_ + tt) * Q_ + q2] = tile[idx & 31][tt];
    }
    if (tid < T_) {
        unsigned long long best = ~0ull;
        int qmax = min(32, Q_ - q0);
        for (int k = 0; k < qmax; k++) {
            unsigned long long key =
                ((unsigned long long)order_f(tile[k][tid]) << 32) | (unsigned)(q0 + k);
            if (key < best) best = key;
        }
        atomicMax(&g_rowmin[b * T_ + tid], ~best);
    }
}

// ---------------------------------------------------------------------------
// Kernel 1.5 (R11, known-good): per-row bottom-[100,128] candidate selection.
// ---------------------------------------------------------------------------
__global__ void __launch_bounds__(256) cand_kernel() {
    int gw = (blockIdx.x * 256 + threadIdx.x) >> 5;    // row id = b*T + t
    int lane = threadIdx.x & 31;
    if (gw >= B_ * T_) return;
    const float* row = g_costT + (size_t)gw * Q_;

    unsigned long long key[29];
    #pragma unroll
    for (int k = 0; k < 29; k++) {
        int j = lane + (k << 5);
        key[k] = (j < Q_)
          ? (((unsigned long long)order_f(__ldg(row + j)) << 32) | (unsigned)j)
          : ~0ull;
    }

    unsigned lo = 0, hi = 0xFFFFFFFFu;
    unsigned tau = 0; int n = -1;
    for (int it = 0; it < 34 && n < 0; it++) {
        unsigned mid = (it < 32) ? (lo + ((hi - lo) >> 1)) : hi;
        int c = 0;
        #pragma unroll
        for (int k = 0; k < 29; k++)
            c += ((unsigned)(key[k] >> 32) <= mid) ? 1 : 0;
        c = __reduce_add_sync(0xFFFFFFFFu, c);
        if (c >= 100 && c <= NCAND) { tau = mid; n = c; }
        else if (c > NCAND) hi = mid;
        else lo = mid + 1;
    }

    bool tie = false; unsigned jcut = 0;
    if (n < 0) {
        tau = hi;
        int n1 = 0;
        #pragma unroll
        for (int k = 0; k < 29; k++)
            n1 += ((unsigned)(key[k] >> 32) < tau) ? 1 : 0;
        n1 = __reduce_add_sync(0xFFFFFFFFu, n1);
        int need = 100 - n1;
        unsigned jlo = 0, jhi = 1023;
        for (int it = 0; it < 10; it++) {
            unsigned jm = (jlo + jhi) >> 1;
            int c = 0;
            #pragma unroll
            for (int k = 0; k < 29; k++) {
                unsigned v = (unsigned)(key[k] >> 32);
                unsigned j = (unsigned)(key[k] & 0xFFFFFFFFu);
                c += (v == tau && j <= jm) ? 1 : 0;
            }
            c = __reduce_add_sync(0xFFFFFFFFu, c);
            if (c >= need) jhi = jm; else jlo = jm + 1;
        }
        jcut = jhi; tie = true;
    }

    unsigned long long* dst = g_cand + ((size_t)gw << 7);
    int base = 0;
    #pragma unroll
    for (int k = 0; k < 29; k++) {
        unsigned v = (unsigned)(key[k] >> 32);
        unsigned j = (unsigned)(key[k] & 0xFFFFFFFFu);
        bool qv = tie ? ((v < tau) || (v == tau && j <= jcut)) : (v <= tau);
        qv = qv && (j < (unsigned)Q_);
        unsigned mask = __ballot_sync(0xFFFFFFFFu, qv);
        if (qv) dst[base + __popc(mask & ((1u << lane) - 1))] = key[k];
        base += __popc(mask);
    }
    if (lane == 0) g_ncand[gw] = base;
}

// ---------------------------------------------------------------------------
// Kernel 2 (R11 verbatim, known-good): JV, greedy rowmin init +
// matched/free-split SAP. Warps 0-3: matched columns in registers;
// warps 4-7: candidate-list probe for the free minimum.
// ---------------------------------------------------------------------------
__global__ void __launch_bounds__(NTH) hungarian_kernel(float* __restrict__ out,
                                                        int writeIdx) {
    int b = blockIdx.x;
    const float* cost = g_costT + (size_t)b * T_ * Q_;

    __shared__ float u[T_ + 1];
    __shared__ int p[Q_];
    __shared__ int sway[Q_];
    __shared__ unsigned long long keybuf[2][8];
    __shared__ int mlist[T_];
    __shared__ int ncand_s[T_];
    __shared__ int argj[T_];
    __shared__ int rowmatch[T_];
    __shared__ int colarr[T_];
    __shared__ int nm_s;

    int tid = threadIdx.x, lane = tid & 31, wid = tid >> 5;

    for (int j = tid; j < Q_; j += NTH) p[j] = -1;
    if (tid < T_) {
        unsigned long long k = ~g_rowmin[b * T_ + tid];
        argj[tid] = (int)(k & 0xFFFFFFFFu);
        u[tid] = unorder_f((unsigned)(k >> 32));
        ncand_s[tid] = g_ncand[b * T_ + tid];
    }
    if (tid == 0) u[T_] = 0.f;
    __syncthreads();

    if (tid == 0) {
        int nm = 0;
        for (int i = 0; i < T_; i++) {
            int j = argj[i];
            if (p[j] < 0) { p[j] = i; rowmatch[i] = 1; mlist[nm++] = j; }
            else rowmatch[i] = 0;
        }
        nm_s = nm;
    }
    __syncthreads();

    // per-slot matched-column registers (slot = tid, threads 0..127)
    int myj = -1;
    float myv = 0.f;
    unsigned myminv = ~0u;
    bool myused = false;

    for (int i = 0; i < T_; i++) {
        if (rowmatch[i]) continue;
        int nm = nm_s;
        if (tid < nm && myj < 0) { myj = mlist[tid]; myv = 0.f; }
        myminv = 0xFFFFFFFEu; myused = false;
        unsigned long long freebest = ~0ull;
        int freepred = Q_;

        int j0 = Q_, i0 = i, iter = 0, j1;
        float shift = 0.f, Sf;

        while (true) {
            float base = shift - u[i0];
            unsigned bo = 0xFFFFFFFFu, bj = 0xFFFFFFFFu;
            if (tid < 128) {                          // matched side
                if (tid < nm && !myused) {
                    float cur = __ldg(cost + (size_t)i0 * Q_ + myj) - myv + base;
                    unsigned co = order_f(cur);
                    if (co < myminv) { myminv = co; sway[myj] = j0; }
                    bo = myminv; bj = (unsigned)myj;
                }
            } else {                                  // free side (candidates)
                int ci = tid - 128;
                if (ci < ncand_s[i0]) {
                    unsigned long long ck =
                        __ldg(&g_cand[((size_t)(b * T_ + i0) << 7) + ci]);
                    int j = (int)(ck & 0xFFFFFFFFu);
                    if (p[j] < 0) {
                        float val = unorder_f((unsigned)(ck >> 32)) + base;
                        bo = order_f(val); bj = (unsigned)j;
                    }
                }
            }
            unsigned m = __reduce_min_sync(0xFFFFFFFFu, bo);
            unsigned jc = (bo == m) ? bj : 0xFFFFFFFFu;
            unsigned jm = __reduce_min_sync(0xFFFFFFFFu, jc);
            int buf = iter & 1;
            if (lane == 0) keybuf[buf][wid] = ((unsigned long long)m << 32) | jm;
            __syncthreads();

            const unsigned long long* kb = keybuf[buf];
            unsigned long long m0 = kb[0] < kb[2] ? kb[0] : kb[2];
            unsigned long long m1 = kb[1] < kb[3] ? kb[1] : kb[3];
            unsigned long long mpart = m0 < m1 ? m0 : m1;
            unsigned long long f0 = kb[4] < kb[6] ? kb[4] : kb[6];
            unsigned long long f1 = kb[5] < kb[7] ? kb[5] : kb[7];
            unsigned long long fpart = f0 < f1 ? f0 : f1;
            if (fpart < freebest) { freebest = fpart; freepred = j0; }
            unsigned long long tot = mpart < freebest ? mpart : freebest;
            j1 = (int)(tot & 0xFFFFFFFFu);
            Sf = unorder_f((unsigned)(tot >> 32));

            int i0n = p[j1];
            if (i0n < 0) break;                       // free column -> augment

            if (myj == j1) myused = true;             // owner freezes its dist
            j0 = j1; i0 = i0n; shift = Sf; iter++;
        }

        // deferred dual updates (used matched columns only; free v stays 0)
        if (tid < nm && myused) {
            float diff = Sf - unorder_f(myminv);
            myv -= diff;
            u[p[myj]] += diff;                        // rows distinct
        }
        if (tid == 0) u[i] += Sf;
        __syncthreads();                              // duals read p pre-augment

        if (tid == 0) {
            sway[j1] = freepred;
            int j = j1;
            while (j != Q_) {
                int jn = sway[j];
                p[j] = (jn == Q_) ? i : p[jn];
                j = jn;
            }
            rowmatch[i] = 1;
            mlist[nm_s] = j1;                         // new matched column
            nm_s = nm_s + 1;
        }
        __syncthreads();
    }

    // write indices sorted by query (rank via counting)
    for (int j = tid; j < Q_; j += NTH) {
        int r = p[j];
        if (r >= 0) colarr[r] = j;
    }
    __syncthreads();

    if (writeIdx) {
        float* oidx = out + (size_t)B_ * Q_ * T_;
        if (tid < T_) {
            int c = colarr[tid];
            int rank = 0;
            for (int s = 0; s < T_; s++) rank += (colarr[s] < c);
            oidx[(size_t)b * T_ + rank] = (float)c;                      // pred_idx
            oidx[(size_t)B_ * T_ + (size_t)b * T_ + rank] = (float)tid;  // tgt_idx
        }
    }

    // reset rowmin identity for the next graph replay
    if (tid < T_) g_rowmin[b * T_ + tid] = 0ull;
}

// ---------------------------------------------------------------------------
extern "C" void kernel_launch(void* const* d_in, const int* in_sizes, int n_in,
                              void* d_out, int out_size) {
    const float* logits = (const float*)d_in[0];
    const float* pboxes = (const float*)d_in[1];
    const int*   labels = (const int*)d_in[2];
    const float* tboxes = (const float*)d_in[3];
    float* out = (float*)d_out;

    dim3 tg((Q_ + 31) / 32, B_);
    cost_fused_kernel<<<tg, NTC>>>(logits, pboxes, labels, tboxes, out);

    int nrows = B_ * T_;
    cand_kernel<<<(nrows * 32 + 255) / 256, 256>>>();

    int writeIdx = (out_size >= (int)((long long)B_ * Q_ * T_ + 2LL * B_ * T_)) ? 1 : 0;
    hungarian_kernel<<<B_, NTH>>>(out, writeIdx);
}